// round 2
// baseline (speedup 1.0000x reference)
#include <cuda_runtime.h>
#include <math.h>

#define BATCH   4096
#define NBLK    66
#define XDIM    264      // 66 * 4
#define PHI_H   256
#define PHI_OUT 64
#define RHO_H   256
#define WARPS_PER_BLOCK 8

// Global scratch for the cross-batch max (ordered-uint encoded float).
__device__ unsigned g_maxkey;

// Monotonic float->uint key: preserves ordering for all finite floats.
__device__ __forceinline__ unsigned fkey(float f) {
    unsigned b = __float_as_uint(f);
    return (b & 0x80000000u) ? ~b : (b | 0x80000000u);
}
__device__ __forceinline__ float kinv(unsigned k) {
    unsigned b = (k & 0x80000000u) ? (k & 0x7fffffffu) : ~k;
    return __uint_as_float(b);
}

__global__ void bn_init_kernel() { g_maxkey = 0u; }

__global__ __launch_bounds__(256) void bn_main_kernel(
    const float* __restrict__ x,
    const float* __restrict__ pw1, const float* __restrict__ pb1,
    const float* __restrict__ pw2, const float* __restrict__ pb2,
    const float* __restrict__ rw1, const float* __restrict__ rb1,
    const float* __restrict__ rw2, const float* __restrict__ rb2,
    float* __restrict__ out)
{
    __shared__ float xs[WARPS_PER_BLOCK][XDIM];
    __shared__ float Hs[WARPS_PER_BLOCK][PHI_H];
    __shared__ float Xs[WARPS_PER_BLOCK][PHI_OUT];
    __shared__ unsigned s_max;

    const int tid  = threadIdx.x;
    const int w    = tid >> 5;
    const int lane = tid & 31;
    if (tid == 0) s_max = 0u;

    const int b = blockIdx.x * WARPS_PER_BLOCK + w;   // one batch row per warp

    // ---- stage x row into shared (coalesced) ----
    const float* xrow = x + (size_t)b * XDIM;
    for (int i = lane; i < XDIM; i += 32) xs[w][i] = xrow[i];
    __syncwarp();

    // ---- preload layer-1 weights for my 8 hidden units (j = lane + 32k) ----
    float w1r[4][8], b1r[8];
    #pragma unroll
    for (int k = 0; k < 8; k++) {
        const int j = lane + 32 * k;
        b1r[k] = __ldg(pb1 + j);
        #pragma unroll
        for (int r = 0; r < 4; r++) w1r[r][k] = __ldg(pw1 + r * PHI_H + j);
    }

    // ---- layer 1 + block-sum:  H_j = sum_n relu(s_n . w1_j + b1_j) ----
    float H[8];
    #pragma unroll
    for (int k = 0; k < 8; k++) H[k] = 0.f;

    for (int n = 0; n < NBLK; n++) {
        const float4 s = *reinterpret_cast<const float4*>(&xs[w][4 * n]);
        #pragma unroll
        for (int k = 0; k < 8; k++) {
            float t = b1r[k];
            t = fmaf(w1r[0][k], s.x, t);
            t = fmaf(w1r[1][k], s.y, t);
            t = fmaf(w1r[2][k], s.z, t);
            t = fmaf(w1r[3][k], s.w, t);
            H[k] += fmaxf(t, 0.f);
        }
    }

    #pragma unroll
    for (int k = 0; k < 8; k++) Hs[w][lane + 32 * k] = H[k];
    __syncwarp();

    // ---- X = H @ W2 + 66*b2 : lane owns output cols {2*lane, 2*lane+1} ----
    float x0 = 66.f * __ldg(pb2 + 2 * lane);
    float x1 = 66.f * __ldg(pb2 + 2 * lane + 1);
    #pragma unroll 4
    for (int j = 0; j < PHI_H; j++) {
        const float h = Hs[w][j];
        const float2 wv = __ldg(reinterpret_cast<const float2*>(pw2 + j * PHI_OUT + 2 * lane));
        x0 = fmaf(h, wv.x, x0);
        x1 = fmaf(h, wv.y, x1);
    }
    Xs[w][2 * lane]     = x0;
    Xs[w][2 * lane + 1] = x1;
    __syncwarp();

    // ---- rho: h2_j = relu(X . rw1[:,j] + rb1_j);  a = h2 @ rw2 ----
    float a0 = 0.f, a1 = 0.f;
    #pragma unroll
    for (int k = 0; k < 8; k++) {
        const int j = lane + 32 * k;
        float t = __ldg(rb1 + j);
        #pragma unroll 8
        for (int i = 0; i < PHI_OUT; i++) {
            t = fmaf(Xs[w][i], __ldg(rw1 + i * RHO_H + j), t);
        }
        t = fmaxf(t, 0.f);
        const float2 rv = __ldg(reinterpret_cast<const float2*>(rw2 + 2 * j));
        a0 = fmaf(t, rv.x, a0);
        a1 = fmaf(t, rv.y, a1);
    }

    // ---- barrier term over neighbors n = 2..65 (2 per lane) ----
    float bx = 0.f, by = 0.f;
    #pragma unroll
    for (int q = 0; q < 2; q++) {
        const int n = 2 + lane + 32 * q;
        const float px = xs[w][4 * n], py = xs[w][4 * n + 1];
        const float d  = sqrtf(px * px + py * py);
        const float dm = d - 0.15f;
        const float inv = 1.f / (dm * dm);
        bx -= px * inv;
        by -= py * inv;
    }

    // ---- warp butterfly reduce (a0, a1, bx, by) ----
    #pragma unroll
    for (int off = 16; off > 0; off >>= 1) {
        a0 += __shfl_xor_sync(0xffffffff, a0, off);
        a1 += __shfl_xor_sync(0xffffffff, a1, off);
        bx += __shfl_xor_sync(0xffffffff, bx, off);
        by += __shfl_xor_sync(0xffffffff, by, off);
    }

    __syncthreads();  // orders s_max init (thread 0) before atomics below
    if (lane == 0) {
        const float r0 = 2.0f * tanhf(a0 + __ldg(rb2))     + bx;
        const float r1 = 2.0f * tanhf(a1 + __ldg(rb2 + 1)) + by;
        out[2 * b]     = r0;
        out[2 * b + 1] = r1;
        const unsigned k = max(fkey(r0), fkey(r1));
        atomicMax(&s_max, k);
    }
    __syncthreads();
    if (tid == 0) atomicMax(&g_maxkey, s_max);
}

__global__ void bn_scale_kernel(float* __restrict__ out) {
    const int i = blockIdx.x * blockDim.x + threadIdx.x;
    if (i >= BATCH * 2) return;
    const float mx    = kinv(g_maxkey);
    const float scale = 2.0f / mx;
    const float v = out[i];
    out[i] = (scale < 1.0f) ? v * scale : v;
}

extern "C" void kernel_launch(void* const* d_in, const int* in_sizes, int n_in,
                              void* d_out, int out_size)
{
    const float* x   = (const float*)d_in[0];
    const float* pw1 = (const float*)d_in[1];
    const float* pb1 = (const float*)d_in[2];
    const float* pw2 = (const float*)d_in[3];
    const float* pb2 = (const float*)d_in[4];
    const float* rw1 = (const float*)d_in[5];
    const float* rb1 = (const float*)d_in[6];
    const float* rw2 = (const float*)d_in[7];
    const float* rb2 = (const float*)d_in[8];
    float* out = (float*)d_out;

    bn_init_kernel<<<1, 1>>>();
    bn_main_kernel<<<BATCH / WARPS_PER_BLOCK, 256>>>(
        x, pw1, pb1, pw2, pb2, rw1, rb1, rw2, rb2, out);
    bn_scale_kernel<<<(BATCH * 2 + 255) / 256, 256>>>(out);
}